// round 12
// baseline (speedup 1.0000x reference)
#include <cuda_runtime.h>
#include <math.h>

// Problem constants
#define Bb 2
#define Ss 2048
#define Dd 1024
#define Hh 16
#define DEPTH 64
#define MROWS (Bb * Ss)                 // 4096
#define NKBLK (Ss / 128)                // 16 k-blocks per attn row (pass-1 partials)

static const long long OUT_ELEMS  = (long long)Bb * Ss * Dd;          // 4,194,304
static const long long ATTN_ELEMS = (long long)Bb * Hh * Ss * Ss;     // 134,217,728

// ---------------- device scratch (no cudaMalloc allowed) ----------------
__device__ float g_Q[MROWS * Dd];
__device__ float g_K[MROWS * Dd];
__device__ float g_V[MROWS * Dd];
__device__ float g_Z[MROWS * Dd];
__device__ float g_attn[(size_t)Bb * Hh * Ss * Ss];   // 512 MB bss fallback
__device__ float g_out[MROWS * Dd];                   // fallback
__device__ float g_rowpart[(size_t)Bb * Hh * Ss * NKBLK];  // partial row sums
__device__ float g_inv[(size_t)Bb * Hh * Ss];              // 1/rowsum

// ---------------- tf32 helpers ----------------
__device__ __forceinline__ unsigned f2tf(float f) {
    unsigned u;
    asm("cvt.rna.tf32.f32 %0, %1;" : "=r"(u) : "f"(f));
    return u;
}

__device__ __forceinline__ void mma8(float* d, const unsigned* a, const unsigned* b) {
    asm volatile(
        "mma.sync.aligned.m16n8k8.row.col.f32.tf32.tf32.f32 "
        "{%0,%1,%2,%3}, {%4,%5,%6,%7}, {%8,%9}, {%0,%1,%2,%3};\n"
        : "+f"(d[0]), "+f"(d[1]), "+f"(d[2]), "+f"(d[3])
        : "r"(a[0]), "r"(a[1]), "r"(a[2]), "r"(a[3]),
          "r"(b[0]), "r"(b[1]));
}

// ---------------------------------------------------------------
// Tensor-core GEMM body: C = A @ B + bias. BM=BN=128, BK=16, 256 thr,
// warp tile 64x32, double buffered.
// ---------------------------------------------------------------
__device__ __forceinline__ void gemm_body(
    const float* __restrict__ A, const float* __restrict__ Bm,
    const float* __restrict__ bias, float* __restrict__ C,
    int M, int N, int K, int bx, int by)
{
    __shared__ unsigned As[2][128][20];
    __shared__ unsigned Bs[2][16][136];

    const int tid  = threadIdx.x;
    const int lane = tid & 31;
    const int wid  = tid >> 5;
    const int gid  = lane >> 2;
    const int tig  = lane & 3;
    const int wm   = wid & 1;
    const int wn   = wid >> 1;
    const int row0 = by * 128;
    const int col0 = bx * 128;

    const int ar = tid >> 2;
    const int ac = (tid & 3) * 4;
    const int br = tid >> 5;
    const int bc = (tid & 31) * 4;

    float acc[4][4][4] = {};

    {
        float4 v0 = *(const float4*)&A[(size_t)(row0 + ar) * K + ac];
        float4 v1 = *(const float4*)&A[(size_t)(row0 + ar + 64) * K + ac];
        As[0][ar][ac+0]=f2tf(v0.x); As[0][ar][ac+1]=f2tf(v0.y);
        As[0][ar][ac+2]=f2tf(v0.z); As[0][ar][ac+3]=f2tf(v0.w);
        As[0][ar+64][ac+0]=f2tf(v1.x); As[0][ar+64][ac+1]=f2tf(v1.y);
        As[0][ar+64][ac+2]=f2tf(v1.z); As[0][ar+64][ac+3]=f2tf(v1.w);
        float4 w0 = *(const float4*)&Bm[(size_t)br * N + col0 + bc];
        float4 w1 = *(const float4*)&Bm[(size_t)(br + 8) * N + col0 + bc];
        Bs[0][br][bc+0]=f2tf(w0.x); Bs[0][br][bc+1]=f2tf(w0.y);
        Bs[0][br][bc+2]=f2tf(w0.z); Bs[0][br][bc+3]=f2tf(w0.w);
        Bs[0][br+8][bc+0]=f2tf(w1.x); Bs[0][br+8][bc+1]=f2tf(w1.y);
        Bs[0][br+8][bc+2]=f2tf(w1.z); Bs[0][br+8][bc+3]=f2tf(w1.w);
    }
    __syncthreads();

    const int T = K >> 4;
    for (int t = 0; t < T; ++t) {
        const int cur = t & 1;
        float4 pa0, pa1, pb0, pb1;
        if (t + 1 < T) {
            const int k0 = (t + 1) << 4;
            pa0 = *(const float4*)&A[(size_t)(row0 + ar) * K + k0 + ac];
            pa1 = *(const float4*)&A[(size_t)(row0 + ar + 64) * K + k0 + ac];
            pb0 = *(const float4*)&Bm[(size_t)(k0 + br) * N + col0 + bc];
            pb1 = *(const float4*)&Bm[(size_t)(k0 + br + 8) * N + col0 + bc];
        }
        #pragma unroll
        for (int ks = 0; ks < 2; ++ks) {
            const int k8 = ks * 8;
            unsigned af[4][4], bf[4][2];
            #pragma unroll
            for (int mt = 0; mt < 4; ++mt) {
                const int rm = wm * 64 + mt * 16;
                af[mt][0] = As[cur][rm + gid    ][k8 + tig    ];
                af[mt][1] = As[cur][rm + gid + 8][k8 + tig    ];
                af[mt][2] = As[cur][rm + gid    ][k8 + tig + 4];
                af[mt][3] = As[cur][rm + gid + 8][k8 + tig + 4];
            }
            #pragma unroll
            for (int nt = 0; nt < 4; ++nt) {
                const int cn = wn * 32 + nt * 8;
                bf[nt][0] = Bs[cur][k8 + tig    ][cn + gid];
                bf[nt][1] = Bs[cur][k8 + tig + 4][cn + gid];
            }
            #pragma unroll
            for (int mt = 0; mt < 4; ++mt)
                #pragma unroll
                for (int nt = 0; nt < 4; ++nt)
                    mma8(acc[mt][nt], af[mt], bf[nt]);
        }
        if (t + 1 < T) {
            const int nb = cur ^ 1;
            As[nb][ar][ac+0]=f2tf(pa0.x); As[nb][ar][ac+1]=f2tf(pa0.y);
            As[nb][ar][ac+2]=f2tf(pa0.z); As[nb][ar][ac+3]=f2tf(pa0.w);
            As[nb][ar+64][ac+0]=f2tf(pa1.x); As[nb][ar+64][ac+1]=f2tf(pa1.y);
            As[nb][ar+64][ac+2]=f2tf(pa1.z); As[nb][ar+64][ac+3]=f2tf(pa1.w);
            Bs[nb][br][bc+0]=f2tf(pb0.x); Bs[nb][br][bc+1]=f2tf(pb0.y);
            Bs[nb][br][bc+2]=f2tf(pb0.z); Bs[nb][br][bc+3]=f2tf(pb0.w);
            Bs[nb][br+8][bc+0]=f2tf(pb1.x); Bs[nb][br+8][bc+1]=f2tf(pb1.y);
            Bs[nb][br+8][bc+2]=f2tf(pb1.z); Bs[nb][br+8][bc+3]=f2tf(pb1.w);
            __syncthreads();
        }
    }

    #pragma unroll
    for (int mt = 0; mt < 4; ++mt) {
        const int row = row0 + wm * 64 + mt * 16 + gid;
        #pragma unroll
        for (int nt = 0; nt < 4; ++nt) {
            const int col = col0 + wn * 32 + nt * 8 + tig * 2;
            const float b0 = bias[col], b1 = bias[col + 1];
            *(float2*)&C[(size_t)row * N + col] =
                make_float2(acc[mt][nt][0] + b0, acc[mt][nt][1] + b1);
            *(float2*)&C[(size_t)(row + 8) * N + col] =
                make_float2(acc[mt][nt][2] + b0, acc[mt][nt][3] + b1);
        }
    }
}

__global__ void __launch_bounds__(256) gemm_tc(
    const float* __restrict__ A, const float* __restrict__ Bm,
    const float* __restrict__ bias, float* __restrict__ C,
    int M, int N, int K)
{
    gemm_body(A, Bm, bias, C, M, N, K, blockIdx.x, blockIdx.y);
}

__global__ void __launch_bounds__(256) qkv_tc(
    const float* __restrict__ A,
    const float* __restrict__ W0, const float* __restrict__ W1, const float* __restrict__ W2,
    const float* __restrict__ b0, const float* __restrict__ b1, const float* __restrict__ b2,
    float* __restrict__ O0, float* __restrict__ O1, float* __restrict__ O2)
{
    const int z = blockIdx.z;
    const float* W = (z == 0) ? W0 : (z == 1) ? W1 : W2;
    const float* bv = (z == 0) ? b0 : (z == 1) ? b1 : b2;
    float* O = (z == 0) ? O0 : (z == 1) ? O1 : O2;
    gemm_body(A, W, bv, O, MROWS, Dd, Dd, blockIdx.x, blockIdx.y);
}

// ---------------------------------------------------------------
// PASS 1: row sums of exp(logits) only — no attn store.
// 512 threads, block 128x128, warp grid 4x4, warp tile 32x32.
// ---------------------------------------------------------------
__global__ void __launch_bounds__(512) logits_sums_tc(
    const float* __restrict__ Q, const float* __restrict__ Km,
    const float* __restrict__ mask, float* __restrict__ rowpart)
{
    __shared__ unsigned Qs[128][36];
    __shared__ unsigned Ks[128][36];
    __shared__ float rsum[128][4];

    const int tid  = threadIdx.x;
    const int lane = tid & 31;
    const int wid  = tid >> 5;
    const int gid  = lane >> 2;
    const int tig  = lane & 3;
    const int wm   = wid & 3;
    const int wn   = wid >> 2;
    const int bh = blockIdx.z, b = bh >> 4, h = bh & 15;
    const int q0 = blockIdx.y * 128, k0 = blockIdx.x * 128;

    const float* Qb = Q  + (size_t)b * Ss * Dd + h * DEPTH;
    const float* Kb = Km + (size_t)b * Ss * Dd + h * DEPTH;

    float acc[2][4][4] = {};

    #pragma unroll
    for (int c = 0; c < 2; ++c) {
        const int d0 = c * 32;
        if (c) __syncthreads();
        #pragma unroll
        for (int i = 0; i < 2; ++i) {
            const int idx = tid + i * 512;
            const int r = idx >> 3, c4 = (idx & 7) * 4;
            float4 v = *(const float4*)&Qb[(size_t)(q0 + r) * Dd + d0 + c4];
            Qs[r][c4+0]=f2tf(v.x); Qs[r][c4+1]=f2tf(v.y);
            Qs[r][c4+2]=f2tf(v.z); Qs[r][c4+3]=f2tf(v.w);
            float4 w = *(const float4*)&Kb[(size_t)(k0 + r) * Dd + d0 + c4];
            Ks[r][c4+0]=f2tf(w.x); Ks[r][c4+1]=f2tf(w.y);
            Ks[r][c4+2]=f2tf(w.z); Ks[r][c4+3]=f2tf(w.w);
        }
        __syncthreads();
        #pragma unroll
        for (int ks = 0; ks < 4; ++ks) {
            const int k8 = ks * 8;
            unsigned af[2][4], bf[4][2];
            #pragma unroll
            for (int mt = 0; mt < 2; ++mt) {
                const int rm = wm * 32 + mt * 16;
                af[mt][0] = Qs[rm + gid    ][k8 + tig    ];
                af[mt][1] = Qs[rm + gid + 8][k8 + tig    ];
                af[mt][2] = Qs[rm + gid    ][k8 + tig + 4];
                af[mt][3] = Qs[rm + gid + 8][k8 + tig + 4];
            }
            #pragma unroll
            for (int nt = 0; nt < 4; ++nt) {
                const int cn = wn * 32 + nt * 8;
                bf[nt][0] = Ks[cn + gid][k8 + tig    ];
                bf[nt][1] = Ks[cn + gid][k8 + tig + 4];
            }
            #pragma unroll
            for (int mt = 0; mt < 2; ++mt)
                #pragma unroll
                for (int nt = 0; nt < 4; ++nt)
                    mma8(acc[mt][nt], af[mt], bf[nt]);
        }
    }

    const float* mb = mask + b * Ss;
    #pragma unroll
    for (int mt = 0; mt < 2; ++mt) {
        const int lrow = wm * 32 + mt * 16 + gid;
        const int row  = q0 + lrow;
        const float mq0 = mb[row], mq1 = mb[row + 8];
        float s0 = 0.0f, s1 = 0.0f;
        #pragma unroll
        for (int nt = 0; nt < 4; ++nt) {
            const int col = wn * 32 + nt * 8 + tig * 2;
            const float mk0 = mb[k0 + col], mk1 = mb[k0 + col + 1];
            float e0 = __expf(acc[mt][nt][0] * 0.125f + fminf(1.0f, mq0 + mk0));
            float e1 = __expf(acc[mt][nt][1] * 0.125f + fminf(1.0f, mq0 + mk1));
            float e2 = __expf(acc[mt][nt][2] * 0.125f + fminf(1.0f, mq1 + mk0));
            float e3 = __expf(acc[mt][nt][3] * 0.125f + fminf(1.0f, mq1 + mk1));
            s0 += e0 + e1;
            s1 += e2 + e3;
        }
        s0 += __shfl_xor_sync(0xffffffffu, s0, 1);
        s0 += __shfl_xor_sync(0xffffffffu, s0, 2);
        s1 += __shfl_xor_sync(0xffffffffu, s1, 1);
        s1 += __shfl_xor_sync(0xffffffffu, s1, 2);
        if (tig == 0) {
            rsum[lrow    ][wn] = s0;
            rsum[lrow + 8][wn] = s1;
        }
    }
    __syncthreads();
    if (tid < 128) {
        float s = rsum[tid][0] + rsum[tid][1] + rsum[tid][2] + rsum[tid][3];
        rowpart[((size_t)bh * Ss + q0 + tid) * NKBLK + blockIdx.x] = s;
    }
}

// ---------------------------------------------------------------
// inv[row] = 1 / sum_kb rowpart[row][kb]
// ---------------------------------------------------------------
__global__ void rowsum_inv(const float* __restrict__ part, float* __restrict__ inv) {
    const int r = blockIdx.x * 256 + threadIdx.x;
    const float4* p = (const float4*)(part + (size_t)r * NKBLK);
    float4 a = p[0], b = p[1], c = p[2], d = p[3];
    float s = ((a.x + a.y) + (a.z + a.w)) + ((b.x + b.y) + (b.z + b.w))
            + ((c.x + c.y) + (c.z + c.w)) + ((d.x + d.y) + (d.z + d.w));
    inv[r] = 1.0f / s;
}

// ---------------------------------------------------------------
// PASS 2 (fused, 512 threads, k-chunk 128): per (bh, q-block 128):
//   recompute S = Q.K^T (MMA, warp grid 4x4 / tiles 32x32),
//   p = exp(S*0.125+mask)*inv, streamed write to attn (__stcs),
//   stage tf32 p in smem, Z += p @ V (warp grid 8x2 / tiles 16x32).
// Smem: Qs[128][68] Ks[128][68] Vs[128][72] Ps[128][132] = 174080 B.
// 16 warps/SM, 2 syncthreads per chunk, 16 chunks.
// ---------------------------------------------------------------
#define QS(r,c) smq[(r)*68+(c)]
#define KS(r,c) smk[(r)*68+(c)]
#define VS(r,c) smv[(r)*72+(c)]
#define PS(r,c) smp[(r)*132+(c)]

__global__ void __launch_bounds__(512, 1) attn_pass2(
    const float* __restrict__ Q, const float* __restrict__ Km,
    const float* __restrict__ V, const float* __restrict__ mask,
    const float* __restrict__ inv, float* __restrict__ attn,
    float* __restrict__ Z)
{
    extern __shared__ unsigned smem_dyn[];
    unsigned* smq = smem_dyn;             // [128][68]
    unsigned* smk = smem_dyn + 8704;      // [128][68]
    unsigned* smv = smem_dyn + 17408;     // [128][72]
    unsigned* smp = smem_dyn + 26624;     // [128][132]

    const int tid  = threadIdx.x;
    const int lane = tid & 31;
    const int wid  = tid >> 5;        // 0..15
    const int gid  = lane >> 2;
    const int tig  = lane & 3;
    const int wqs  = wid & 3;         // S phase: 4 groups over 128 q rows
    const int wks  = wid >> 2;        // S phase: 4 groups over 128 k cols
    const int wqa  = wid & 7;         // AV phase: 8 groups over 128 q rows
    const int wna  = wid >> 3;        // AV phase: 2 groups over 64 d cols
    const int bh = blockIdx.y, b = bh >> 4, h = bh & 15;
    const int q0 = blockIdx.x * 128;

    const float* Qb = Q  + (size_t)b * Ss * Dd + h * DEPTH;
    const float* Kb = Km + (size_t)b * Ss * Dd + h * DEPTH;
    const float* Vb = V  + (size_t)b * Ss * Dd + h * DEPTH;
    const float* mb = mask + b * Ss;

    // load Q tile (128 x 64) as tf32
    #pragma unroll
    for (int i = 0; i < 4; ++i) {
        const int idx = tid + i * 512;
        const int r = idx >> 4, c4 = (idx & 15) * 4;
        float4 v = *(const float4*)&Qb[(size_t)(q0 + r) * Dd + c4];
        QS(r, c4+0)=f2tf(v.x); QS(r, c4+1)=f2tf(v.y);
        QS(r, c4+2)=f2tf(v.z); QS(r, c4+3)=f2tf(v.w);
    }

    // per-thread row constants for the S epilogue (wqs mapping)
    float inv_r[2][2], mqv[2][2];
    #pragma unroll
    for (int mt = 0; mt < 2; ++mt) {
        const int lrow = wqs * 32 + mt * 16 + gid;
        inv_r[mt][0] = inv[(size_t)bh * Ss + q0 + lrow];
        inv_r[mt][1] = inv[(size_t)bh * Ss + q0 + lrow + 8];
        mqv[mt][0] = mb[q0 + lrow];
        mqv[mt][1] = mb[q0 + lrow + 8];
    }

    float acc_z[4][4] = {};

    for (int k0 = 0; k0 < Ss; k0 += 128) {
        __syncthreads();   // prev AV done reading Vs/Ps; prev S done with Ks; Q load visible
        // cooperative load of K, V chunks (128 x 64 each)
        #pragma unroll
        for (int i = 0; i < 4; ++i) {
            const int idx = tid + i * 512;
            const int r = idx >> 4, c4 = (idx & 15) * 4;
            float4 kv = *(const float4*)&Kb[(size_t)(k0 + r) * Dd + c4];
            KS(r, c4+0)=f2tf(kv.x); KS(r, c4+1)=f2tf(kv.y);
            KS(r, c4+2)=f2tf(kv.z); KS(r, c4+3)=f2tf(kv.w);
            float4 vv = *(const float4*)&Vb[(size_t)(k0 + r) * Dd + c4];
            VS(r, c4+0)=f2tf(vv.x); VS(r, c4+1)=f2tf(vv.y);
            VS(r, c4+2)=f2tf(vv.z); VS(r, c4+3)=f2tf(vv.w);
        }
        __syncthreads();

        // ---- S = Q.K^T (128 x 128), warp patch 32x32 ----
        float acc_s[2][4][4] = {};
        #pragma unroll
        for (int ds = 0; ds < 8; ++ds) {
            const int d8 = ds * 8;
            unsigned af[2][4], bf[4][2];
            #pragma unroll
            for (int mt = 0; mt < 2; ++mt) {
                const int rm = wqs * 32 + mt * 16;
                af[mt][0] = QS(rm + gid    , d8 + tig    );
                af[mt][1] = QS(rm + gid + 8, d8 + tig    );
                af[mt][2] = QS(rm + gid    , d8 + tig + 4);
                af[mt][3] = QS(rm + gid + 8, d8 + tig + 4);
            }
            #pragma unroll
            for (int nt = 0; nt < 4; ++nt) {
                const int cn = wks * 32 + nt * 8;
                bf[nt][0] = KS(cn + gid, d8 + tig    );
                bf[nt][1] = KS(cn + gid, d8 + tig + 4);
            }
            #pragma unroll
            for (int mt = 0; mt < 2; ++mt)
                #pragma unroll
                for (int nt = 0; nt < 4; ++nt)
                    mma8(acc_s[mt][nt], af[mt], bf[nt]);
        }

        // ---- epilogue: p = exp(s*0.125 + mask)*inv; stream to attn + stage Ps ----
        #pragma unroll
        for (int mt = 0; mt < 2; ++mt) {
            const int lrow = wqs * 32 + mt * 16 + gid;
            const int row  = q0 + lrow;
            float* o0 = attn + ((size_t)bh * Ss + row) * Ss + k0;
            float* o1 = o0 + (size_t)8 * Ss;
            #pragma unroll
            for (int nt = 0; nt < 4; ++nt) {
                const int col = wks * 32 + nt * 8 + tig * 2;
                const float mk0 = mb[k0 + col], mk1 = mb[k0 + col + 1];
                float e0 = __expf(acc_s[mt][nt][0] * 0.125f + fminf(1.0f, mqv[mt][0] + mk0)) * inv_r[mt][0];
                float e1 = __expf(acc_s[mt][nt][1] * 0.125f + fminf(1.0f, mqv[mt][0] + mk1)) * inv_r[mt][0];
                float e2 = __expf(acc_s[mt][nt][2] * 0.125f + fminf(1.0f, mqv[mt][1] + mk0)) * inv_r[mt][1];
                float e3 = __expf(acc_s[mt][nt][3] * 0.125f + fminf(1.0f, mqv[mt][1] + mk1)) * inv_r[mt][1];
                __stcs((float2*)&o0[col], make_float2(e0, e1));
                __stcs((float2*)&o1[col], make_float2(e2, e3));
                PS(lrow    , col    ) = f2tf(e0);
                PS(lrow    , col + 1) = f2tf(e1);
                PS(lrow + 8, col    ) = f2tf(e2);
                PS(lrow + 8, col + 1) = f2tf(e3);
            }
        }
        __syncthreads();

        // ---- Z += P (128 x 128) @ V (128 x 64), warp patch 16x32 ----
        #pragma unroll
        for (int ks = 0; ks < 16; ++ks) {
            const int kk = ks * 8;
            unsigned af[4], bf[4][2];
            const int rm = wqa * 16;
            af[0] = PS(rm + gid    , kk + tig    );
            af[1] = PS(rm + gid + 8, kk + tig    );
            af[2] = PS(rm + gid    , kk + tig + 4);
            af[3] = PS(rm + gid + 8, kk + tig + 4);
            #pragma unroll
            for (int nt = 0; nt < 4; ++nt) {
                const int cn = wna * 32 + nt * 8;
                bf[nt][0] = VS(kk + tig    , cn + gid);
                bf[nt][1] = VS(kk + tig + 4, cn + gid);
            }
            #pragma unroll
            for (int nt = 0; nt < 4; ++nt)
                mma8(acc_z[nt], af, bf[nt]);
        }
    }

    // Z epilogue (wqa / wna mapping)
    float* Zb = Z + (size_t)b * Ss * Dd + h * DEPTH;
    const int row = q0 + wqa * 16 + gid;
    #pragma unroll
    for (int nt = 0; nt < 4; ++nt) {
        const int col = wna * 32 + nt * 8 + tig * 2;
        *(float2*)&Zb[(size_t)row * Dd + col] = make_float2(acc_z[nt][0], acc_z[nt][1]);
        *(float2*)&Zb[(size_t)(row + 8) * Dd + col] = make_float2(acc_z[nt][2], acc_z[nt][3]);
    }
}

// ---------------------------------------------------------------
extern "C" void kernel_launch(void* const* d_in, const int* in_sizes, int n_in,
                              void* d_out, int out_size) {
    const float* x    = (const float*)d_in[0];
    const float* mask = (const float*)d_in[1];
    const float* Wq   = (const float*)d_in[2];
    const float* bq   = (const float*)d_in[3];
    const float* Wk   = (const float*)d_in[4];
    const float* bk   = (const float*)d_in[5];
    const float* Wv   = (const float*)d_in[6];
    const float* bv   = (const float*)d_in[7];
    const float* Wo   = (const float*)d_in[8];
    const float* bo   = (const float*)d_in[9];

    float *Qb, *Kb, *Vb, *Zb, *attn_scr, *out_scr, *rowpart, *invp;
    cudaGetSymbolAddress((void**)&Qb, g_Q);
    cudaGetSymbolAddress((void**)&Kb, g_K);
    cudaGetSymbolAddress((void**)&Vb, g_V);
    cudaGetSymbolAddress((void**)&Zb, g_Z);
    cudaGetSymbolAddress((void**)&attn_scr, g_attn);
    cudaGetSymbolAddress((void**)&out_scr, g_out);
    cudaGetSymbolAddress((void**)&rowpart, g_rowpart);
    cudaGetSymbolAddress((void**)&invp, g_inv);

    float* out_ptr;
    float* attn_ptr;
    const long long osz = (long long)out_size;
    if (osz >= OUT_ELEMS + ATTN_ELEMS) {
        out_ptr  = (float*)d_out;
        attn_ptr = (float*)d_out + OUT_ELEMS;
    } else if (osz >= ATTN_ELEMS) {
        attn_ptr = (float*)d_out;
        out_ptr  = out_scr;
    } else {
        out_ptr  = (float*)d_out;
        attn_ptr = attn_scr;
    }

    const int PASS2_SMEM = 174080;   // 43520 u32
    cudaFuncSetAttribute(attn_pass2,
                         cudaFuncAttributeMaxDynamicSharedMemorySize, PASS2_SMEM);

    // QKV projections, fused into one launch (grid.z = which projection)
    {
        dim3 grid(Dd / 128, MROWS / 128, 3);
        qkv_tc<<<grid, 256>>>(x, Wq, Wk, Wv, bq, bk, bv, Qb, Kb, Vb);
    }

    // pass 1: row sums of exp(logits)  (no big store)
    {
        dim3 grid(Ss / 128, Ss / 128, Bb * Hh);
        logits_sums_tc<<<grid, 512>>>(Qb, Kb, mask, rowpart);
    }

    // 1/rowsum
    rowsum_inv<<<(Bb * Hh * Ss) / 256, 256>>>(rowpart, invp);

    // pass 2: recompute S, write normalized attn, Z = attn @ V
    {
        dim3 grid(Ss / 128, Bb * Hh);
        attn_pass2<<<grid, 512, PASS2_SMEM>>>(Qb, Kb, Vb, mask, invp, attn_ptr, Zb);
    }

    // out = Z @ Wo + bo
    {
        dim3 grid(Dd / 128, MROWS / 128);
        gemm_tc<<<grid, 256>>>(Zb, Wo, bo, out_ptr, MROWS, Dd, Dd);
    }
}

// round 13
// speedup vs baseline: 1.0582x; 1.0582x over previous
#include <cuda_runtime.h>
#include <math.h>

// Problem constants
#define Bb 2
#define Ss 2048
#define Dd 1024
#define Hh 16
#define DEPTH 64
#define MROWS (Bb * Ss)                 // 4096
#define NKBLK (Ss / 128)                // 16 k-blocks per attn row (pass-1 partials)

static const long long OUT_ELEMS  = (long long)Bb * Ss * Dd;          // 4,194,304
static const long long ATTN_ELEMS = (long long)Bb * Hh * Ss * Ss;     // 134,217,728

// ---------------- device scratch (no cudaMalloc allowed) ----------------
__device__ float g_Q[MROWS * Dd];
__device__ float g_K[MROWS * Dd];
__device__ float g_V[MROWS * Dd];
__device__ float g_Z[MROWS * Dd];
__device__ float g_attn[(size_t)Bb * Hh * Ss * Ss];   // 512 MB bss fallback
__device__ float g_out[MROWS * Dd];                   // fallback
__device__ float g_rowpart[(size_t)Bb * Hh * Ss * NKBLK];  // partial row sums
__device__ float g_inv[(size_t)Bb * Hh * Ss];              // 1/rowsum

// ---------------- tf32 helpers ----------------
__device__ __forceinline__ unsigned f2tf(float f) {
    unsigned u;
    asm("cvt.rna.tf32.f32 %0, %1;" : "=r"(u) : "f"(f));
    return u;
}

__device__ __forceinline__ void mma8(float* d, const unsigned* a, const unsigned* b) {
    asm volatile(
        "mma.sync.aligned.m16n8k8.row.col.f32.tf32.tf32.f32 "
        "{%0,%1,%2,%3}, {%4,%5,%6,%7}, {%8,%9}, {%0,%1,%2,%3};\n"
        : "+f"(d[0]), "+f"(d[1]), "+f"(d[2]), "+f"(d[3])
        : "r"(a[0]), "r"(a[1]), "r"(a[2]), "r"(a[3]),
          "r"(b[0]), "r"(b[1]));
}

// ---------------------------------------------------------------
// Tensor-core GEMM body: C = A @ B + bias. BM=BN=128, BK=16, 256 thr,
// warp tile 64x32, double buffered.
// ---------------------------------------------------------------
__device__ __forceinline__ void gemm_body(
    const float* __restrict__ A, const float* __restrict__ Bm,
    const float* __restrict__ bias, float* __restrict__ C,
    int M, int N, int K, int bx, int by)
{
    __shared__ unsigned As[2][128][20];
    __shared__ unsigned Bs[2][16][136];

    const int tid  = threadIdx.x;
    const int lane = tid & 31;
    const int wid  = tid >> 5;
    const int gid  = lane >> 2;
    const int tig  = lane & 3;
    const int wm   = wid & 1;
    const int wn   = wid >> 1;
    const int row0 = by * 128;
    const int col0 = bx * 128;

    const int ar = tid >> 2;
    const int ac = (tid & 3) * 4;
    const int br = tid >> 5;
    const int bc = (tid & 31) * 4;

    float acc[4][4][4] = {};

    {
        float4 v0 = *(const float4*)&A[(size_t)(row0 + ar) * K + ac];
        float4 v1 = *(const float4*)&A[(size_t)(row0 + ar + 64) * K + ac];
        As[0][ar][ac+0]=f2tf(v0.x); As[0][ar][ac+1]=f2tf(v0.y);
        As[0][ar][ac+2]=f2tf(v0.z); As[0][ar][ac+3]=f2tf(v0.w);
        As[0][ar+64][ac+0]=f2tf(v1.x); As[0][ar+64][ac+1]=f2tf(v1.y);
        As[0][ar+64][ac+2]=f2tf(v1.z); As[0][ar+64][ac+3]=f2tf(v1.w);
        float4 w0 = *(const float4*)&Bm[(size_t)br * N + col0 + bc];
        float4 w1 = *(const float4*)&Bm[(size_t)(br + 8) * N + col0 + bc];
        Bs[0][br][bc+0]=f2tf(w0.x); Bs[0][br][bc+1]=f2tf(w0.y);
        Bs[0][br][bc+2]=f2tf(w0.z); Bs[0][br][bc+3]=f2tf(w0.w);
        Bs[0][br+8][bc+0]=f2tf(w1.x); Bs[0][br+8][bc+1]=f2tf(w1.y);
        Bs[0][br+8][bc+2]=f2tf(w1.z); Bs[0][br+8][bc+3]=f2tf(w1.w);
    }
    __syncthreads();

    const int T = K >> 4;
    for (int t = 0; t < T; ++t) {
        const int cur = t & 1;
        float4 pa0, pa1, pb0, pb1;
        if (t + 1 < T) {
            const int k0 = (t + 1) << 4;
            pa0 = *(const float4*)&A[(size_t)(row0 + ar) * K + k0 + ac];
            pa1 = *(const float4*)&A[(size_t)(row0 + ar + 64) * K + k0 + ac];
            pb0 = *(const float4*)&Bm[(size_t)(k0 + br) * N + col0 + bc];
            pb1 = *(const float4*)&Bm[(size_t)(k0 + br + 8) * N + col0 + bc];
        }
        #pragma unroll
        for (int ks = 0; ks < 2; ++ks) {
            const int k8 = ks * 8;
            unsigned af[4][4], bf[4][2];
            #pragma unroll
            for (int mt = 0; mt < 4; ++mt) {
                const int rm = wm * 64 + mt * 16;
                af[mt][0] = As[cur][rm + gid    ][k8 + tig    ];
                af[mt][1] = As[cur][rm + gid + 8][k8 + tig    ];
                af[mt][2] = As[cur][rm + gid    ][k8 + tig + 4];
                af[mt][3] = As[cur][rm + gid + 8][k8 + tig + 4];
            }
            #pragma unroll
            for (int nt = 0; nt < 4; ++nt) {
                const int cn = wn * 32 + nt * 8;
                bf[nt][0] = Bs[cur][k8 + tig    ][cn + gid];
                bf[nt][1] = Bs[cur][k8 + tig + 4][cn + gid];
            }
            #pragma unroll
            for (int mt = 0; mt < 4; ++mt)
                #pragma unroll
                for (int nt = 0; nt < 4; ++nt)
                    mma8(acc[mt][nt], af[mt], bf[nt]);
        }
        if (t + 1 < T) {
            const int nb = cur ^ 1;
            As[nb][ar][ac+0]=f2tf(pa0.x); As[nb][ar][ac+1]=f2tf(pa0.y);
            As[nb][ar][ac+2]=f2tf(pa0.z); As[nb][ar][ac+3]=f2tf(pa0.w);
            As[nb][ar+64][ac+0]=f2tf(pa1.x); As[nb][ar+64][ac+1]=f2tf(pa1.y);
            As[nb][ar+64][ac+2]=f2tf(pa1.z); As[nb][ar+64][ac+3]=f2tf(pa1.w);
            Bs[nb][br][bc+0]=f2tf(pb0.x); Bs[nb][br][bc+1]=f2tf(pb0.y);
            Bs[nb][br][bc+2]=f2tf(pb0.z); Bs[nb][br][bc+3]=f2tf(pb0.w);
            Bs[nb][br+8][bc+0]=f2tf(pb1.x); Bs[nb][br+8][bc+1]=f2tf(pb1.y);
            Bs[nb][br+8][bc+2]=f2tf(pb1.z); Bs[nb][br+8][bc+3]=f2tf(pb1.w);
            __syncthreads();
        }
    }

    #pragma unroll
    for (int mt = 0; mt < 4; ++mt) {
        const int row = row0 + wm * 64 + mt * 16 + gid;
        #pragma unroll
        for (int nt = 0; nt < 4; ++nt) {
            const int col = col0 + wn * 32 + nt * 8 + tig * 2;
            const float b0 = bias[col], b1 = bias[col + 1];
            *(float2*)&C[(size_t)row * N + col] =
                make_float2(acc[mt][nt][0] + b0, acc[mt][nt][1] + b1);
            *(float2*)&C[(size_t)(row + 8) * N + col] =
                make_float2(acc[mt][nt][2] + b0, acc[mt][nt][3] + b1);
        }
    }
}

__global__ void __launch_bounds__(256) gemm_tc(
    const float* __restrict__ A, const float* __restrict__ Bm,
    const float* __restrict__ bias, float* __restrict__ C,
    int M, int N, int K)
{
    gemm_body(A, Bm, bias, C, M, N, K, blockIdx.x, blockIdx.y);
}

__global__ void __launch_bounds__(256) qkv_tc(
    const float* __restrict__ A,
    const float* __restrict__ W0, const float* __restrict__ W1, const float* __restrict__ W2,
    const float* __restrict__ b0, const float* __restrict__ b1, const float* __restrict__ b2,
    float* __restrict__ O0, float* __restrict__ O1, float* __restrict__ O2)
{
    const int z = blockIdx.z;
    const float* W = (z == 0) ? W0 : (z == 1) ? W1 : W2;
    const float* bv = (z == 0) ? b0 : (z == 1) ? b1 : b2;
    float* O = (z == 0) ? O0 : (z == 1) ? O1 : O2;
    gemm_body(A, W, bv, O, MROWS, Dd, Dd, blockIdx.x, blockIdx.y);
}

// ---------------------------------------------------------------
// PASS 1: row sums of exp(logits) only — no attn store.
// 512 threads, block 128x128, warp grid 4x4, warp tile 32x32.
// ---------------------------------------------------------------
__global__ void __launch_bounds__(512) logits_sums_tc(
    const float* __restrict__ Q, const float* __restrict__ Km,
    const float* __restrict__ mask, float* __restrict__ rowpart)
{
    __shared__ unsigned Qs[128][36];
    __shared__ unsigned Ks[128][36];
    __shared__ float rsum[128][4];

    const int tid  = threadIdx.x;
    const int lane = tid & 31;
    const int wid  = tid >> 5;
    const int gid  = lane >> 2;
    const int tig  = lane & 3;
    const int wm   = wid & 3;
    const int wn   = wid >> 2;
    const int bh = blockIdx.z, b = bh >> 4, h = bh & 15;
    const int q0 = blockIdx.y * 128, k0 = blockIdx.x * 128;

    const float* Qb = Q  + (size_t)b * Ss * Dd + h * DEPTH;
    const float* Kb = Km + (size_t)b * Ss * Dd + h * DEPTH;

    float acc[2][4][4] = {};

    #pragma unroll
    for (int c = 0; c < 2; ++c) {
        const int d0 = c * 32;
        if (c) __syncthreads();
        #pragma unroll
        for (int i = 0; i < 2; ++i) {
            const int idx = tid + i * 512;
            const int r = idx >> 3, c4 = (idx & 7) * 4;
            float4 v = *(const float4*)&Qb[(size_t)(q0 + r) * Dd + d0 + c4];
            Qs[r][c4+0]=f2tf(v.x); Qs[r][c4+1]=f2tf(v.y);
            Qs[r][c4+2]=f2tf(v.z); Qs[r][c4+3]=f2tf(v.w);
            float4 w = *(const float4*)&Kb[(size_t)(k0 + r) * Dd + d0 + c4];
            Ks[r][c4+0]=f2tf(w.x); Ks[r][c4+1]=f2tf(w.y);
            Ks[r][c4+2]=f2tf(w.z); Ks[r][c4+3]=f2tf(w.w);
        }
        __syncthreads();
        #pragma unroll
        for (int ks = 0; ks < 4; ++ks) {
            const int k8 = ks * 8;
            unsigned af[2][4], bf[4][2];
            #pragma unroll
            for (int mt = 0; mt < 2; ++mt) {
                const int rm = wm * 32 + mt * 16;
                af[mt][0] = Qs[rm + gid    ][k8 + tig    ];
                af[mt][1] = Qs[rm + gid + 8][k8 + tig    ];
                af[mt][2] = Qs[rm + gid    ][k8 + tig + 4];
                af[mt][3] = Qs[rm + gid + 8][k8 + tig + 4];
            }
            #pragma unroll
            for (int nt = 0; nt < 4; ++nt) {
                const int cn = wn * 32 + nt * 8;
                bf[nt][0] = Ks[cn + gid][k8 + tig    ];
                bf[nt][1] = Ks[cn + gid][k8 + tig + 4];
            }
            #pragma unroll
            for (int mt = 0; mt < 2; ++mt)
                #pragma unroll
                for (int nt = 0; nt < 4; ++nt)
                    mma8(acc[mt][nt], af[mt], bf[nt]);
        }
    }

    const float* mb = mask + b * Ss;
    #pragma unroll
    for (int mt = 0; mt < 2; ++mt) {
        const int lrow = wm * 32 + mt * 16 + gid;
        const int row  = q0 + lrow;
        const float mq0 = mb[row], mq1 = mb[row + 8];
        float s0 = 0.0f, s1 = 0.0f;
        #pragma unroll
        for (int nt = 0; nt < 4; ++nt) {
            const int col = wn * 32 + nt * 8 + tig * 2;
            const float mk0 = mb[k0 + col], mk1 = mb[k0 + col + 1];
            float e0 = __expf(acc[mt][nt][0] * 0.125f + fminf(1.0f, mq0 + mk0));
            float e1 = __expf(acc[mt][nt][1] * 0.125f + fminf(1.0f, mq0 + mk1));
            float e2 = __expf(acc[mt][nt][2] * 0.125f + fminf(1.0f, mq1 + mk0));
            float e3 = __expf(acc[mt][nt][3] * 0.125f + fminf(1.0f, mq1 + mk1));
            s0 += e0 + e1;
            s1 += e2 + e3;
        }
        s0 += __shfl_xor_sync(0xffffffffu, s0, 1);
        s0 += __shfl_xor_sync(0xffffffffu, s0, 2);
        s1 += __shfl_xor_sync(0xffffffffu, s1, 1);
        s1 += __shfl_xor_sync(0xffffffffu, s1, 2);
        if (tig == 0) {
            rsum[lrow    ][wn] = s0;
            rsum[lrow + 8][wn] = s1;
        }
    }
    __syncthreads();
    if (tid < 128) {
        float s = rsum[tid][0] + rsum[tid][1] + rsum[tid][2] + rsum[tid][3];
        rowpart[((size_t)bh * Ss + q0 + tid) * NKBLK + blockIdx.x] = s;
    }
}

// ---------------------------------------------------------------
// inv[row] = 1 / sum_kb rowpart[row][kb]
// ---------------------------------------------------------------
__global__ void rowsum_inv(const float* __restrict__ part, float* __restrict__ inv) {
    const int r = blockIdx.x * 256 + threadIdx.x;
    const float4* p = (const float4*)(part + (size_t)r * NKBLK);
    float4 a = p[0], b = p[1], c = p[2], d = p[3];
    float s = ((a.x + a.y) + (a.z + a.w)) + ((b.x + b.y) + (b.z + b.w))
            + ((c.x + c.y) + (c.z + c.w)) + ((d.x + d.y) + (d.z + d.w));
    inv[r] = 1.0f / s;
}

// ---------------------------------------------------------------
// PASS 2 (register-P): 256 threads (8 warps), per (bh, q-block 128),
// k chunks of 128. Warp grid: wqs = wid&3 (32 q rows), wks = wid>>2
// (64 k cols). Per chunk:
//   S = Q.K^T (warp tile 32x64), epilogue p = exp(S*0.125+mask)*inv
//   -> streamed to attn AND kept in registers as tf32.
//   C-frag -> A-frag conversion via shuffles (no smem round trip).
//   Z_partial += P(32 x 64slice) @ V(64slice x 64) per warp, held in
//   registers across all chunks; cross-warp (wks) reduction via smem
//   once at the end.
// Smem: Qs[128][68] Ks[128][68] Vs[128][72] = 106496 B dynamic.
// ---------------------------------------------------------------
#define QS(r,c) smq[(r)*68+(c)]
#define KS(r,c) smk[(r)*68+(c)]
#define VS(r,c) smv[(r)*72+(c)]

__global__ void __launch_bounds__(256, 1) attn_pass2(
    const float* __restrict__ Q, const float* __restrict__ Km,
    const float* __restrict__ V, const float* __restrict__ mask,
    const float* __restrict__ inv, float* __restrict__ attn,
    float* __restrict__ Z)
{
    extern __shared__ unsigned smem_dyn[];
    unsigned* smq = smem_dyn;             // [128][68]
    unsigned* smk = smem_dyn + 8704;      // [128][68]
    unsigned* smv = smem_dyn + 17408;     // [128][72]

    const int tid  = threadIdx.x;
    const int lane = tid & 31;
    const int wid  = tid >> 5;        // 0..7
    const int gid  = lane >> 2;
    const int tig  = lane & 3;
    const int wqs  = wid & 3;         // 4 groups over 128 q rows (32 each)
    const int wks  = wid >> 2;        // 2 groups over 128 k cols (64 each)
    const int bh = blockIdx.y, b = bh >> 4, h = bh & 15;
    const int q0 = blockIdx.x * 128;

    const float* Qb = Q  + (size_t)b * Ss * Dd + h * DEPTH;
    const float* Kb = Km + (size_t)b * Ss * Dd + h * DEPTH;
    const float* Vb = V  + (size_t)b * Ss * Dd + h * DEPTH;
    const float* mb = mask + b * Ss;

    // load Q tile (128 x 64) as tf32
    #pragma unroll
    for (int i = 0; i < 8; ++i) {
        const int idx = tid + i * 256;
        const int r = idx >> 4, c4 = (idx & 15) * 4;
        float4 v = *(const float4*)&Qb[(size_t)(q0 + r) * Dd + c4];
        QS(r, c4+0)=f2tf(v.x); QS(r, c4+1)=f2tf(v.y);
        QS(r, c4+2)=f2tf(v.z); QS(r, c4+3)=f2tf(v.w);
    }

    // per-thread row constants for the S epilogue
    float inv_r[2][2], mqv[2][2];
    #pragma unroll
    for (int mt = 0; mt < 2; ++mt) {
        const int lrow = wqs * 32 + mt * 16 + gid;
        inv_r[mt][0] = inv[(size_t)bh * Ss + q0 + lrow];
        inv_r[mt][1] = inv[(size_t)bh * Ss + q0 + lrow + 8];
        mqv[mt][0] = mb[q0 + lrow];
        mqv[mt][1] = mb[q0 + lrow + 8];
    }

    // shuffle source lanes for C-frag -> A-frag conversion
    const int src  = (lane & ~3) | (tig >> 1);
    const int src2 = src + 2;
    const bool odd = (tig & 1);

    float acc_z[2][8][4] = {};   // per-warp Z partial: 32 q x 64 d over its k-slice

    for (int k0 = 0; k0 < Ss; k0 += 128) {
        __syncthreads();
        // cooperative load of K, V chunks (128 x 64 each)
        #pragma unroll
        for (int i = 0; i < 8; ++i) {
            const int idx = tid + i * 256;
            const int r = idx >> 4, c4 = (idx & 15) * 4;
            float4 kv = *(const float4*)&Kb[(size_t)(k0 + r) * Dd + c4];
            KS(r, c4+0)=f2tf(kv.x); KS(r, c4+1)=f2tf(kv.y);
            KS(r, c4+2)=f2tf(kv.z); KS(r, c4+3)=f2tf(kv.w);
            float4 vv = *(const float4*)&Vb[(size_t)(k0 + r) * Dd + c4];
            VS(r, c4+0)=f2tf(vv.x); VS(r, c4+1)=f2tf(vv.y);
            VS(r, c4+2)=f2tf(vv.z); VS(r, c4+3)=f2tf(vv.w);
        }
        __syncthreads();

        // ---- S = Q.K^T : warp tile 32 q x 64 k ----
        float acc_s[2][8][4] = {};
        #pragma unroll
        for (int ds = 0; ds < 8; ++ds) {
            const int d8 = ds * 8;
            unsigned af[2][4], bf[8][2];
            #pragma unroll
            for (int mt = 0; mt < 2; ++mt) {
                const int rm = wqs * 32 + mt * 16;
                af[mt][0] = QS(rm + gid    , d8 + tig    );
                af[mt][1] = QS(rm + gid + 8, d8 + tig    );
                af[mt][2] = QS(rm + gid    , d8 + tig + 4);
                af[mt][3] = QS(rm + gid + 8, d8 + tig + 4);
            }
            #pragma unroll
            for (int nt = 0; nt < 8; ++nt) {
                const int cn = wks * 64 + nt * 8;
                bf[nt][0] = KS(cn + gid, d8 + tig    );
                bf[nt][1] = KS(cn + gid, d8 + tig + 4);
            }
            #pragma unroll
            for (int mt = 0; mt < 2; ++mt)
                #pragma unroll
                for (int nt = 0; nt < 8; ++nt)
                    mma8(acc_s[mt][nt], af[mt], bf[nt]);
        }

        // ---- epilogue: p = exp(s*0.125+mask)*inv; store attn; keep tf32 P ----
        unsigned pj[2][8][4];
        #pragma unroll
        for (int mt = 0; mt < 2; ++mt) {
            const int lrow = wqs * 32 + mt * 16 + gid;
            const int row  = q0 + lrow;
            float* o0 = attn + ((size_t)bh * Ss + row) * Ss + k0;
            float* o1 = o0 + (size_t)8 * Ss;
            #pragma unroll
            for (int nt = 0; nt < 8; ++nt) {
                const int col = wks * 64 + nt * 8 + tig * 2;
                const float mk0 = mb[k0 + col], mk1 = mb[k0 + col + 1];
                float e0 = __expf(acc_s[mt][nt][0] * 0.125f + fminf(1.0f, mqv[mt][0] + mk0)) * inv_r[mt][0];
                float e1 = __expf(acc_s[mt][nt][1] * 0.125f + fminf(1.0f, mqv[mt][0] + mk1)) * inv_r[mt][0];
                float e2 = __expf(acc_s[mt][nt][2] * 0.125f + fminf(1.0f, mqv[mt][1] + mk0)) * inv_r[mt][1];
                float e3 = __expf(acc_s[mt][nt][3] * 0.125f + fminf(1.0f, mqv[mt][1] + mk1)) * inv_r[mt][1];
                __stcs((float2*)&o0[col], make_float2(e0, e1));
                __stcs((float2*)&o1[col], make_float2(e2, e3));
                pj[mt][nt][0] = f2tf(e0);
                pj[mt][nt][1] = f2tf(e1);
                pj[mt][nt][2] = f2tf(e2);
                pj[mt][nt][3] = f2tf(e3);
            }
        }

        // ---- Z_partial += P(32 x 64slice) @ V(64slice x 64) ----
        // pj[mt][kf] is the C-frag for k cols [wks*64+kf*8, +8); convert to
        // A-frag via quad shuffles: A(gid,tig) from C col pairs on lane src.
        #pragma unroll
        for (int kf = 0; kf < 8; ++kf) {
            const int kk = wks * 64 + kf * 8;     // chunk-local V rows
            unsigned a[2][4];
            #pragma unroll
            for (int mt = 0; mt < 2; ++mt) {
                unsigned x0 = __shfl_sync(0xffffffffu, pj[mt][kf][0], src);
                unsigned x1 = __shfl_sync(0xffffffffu, pj[mt][kf][1], src);
                unsigned y0 = __shfl_sync(0xffffffffu, pj[mt][kf][2], src);
                unsigned y1 = __shfl_sync(0xffffffffu, pj[mt][kf][3], src);
                unsigned x0b = __shfl_sync(0xffffffffu, pj[mt][kf][0], src2);
                unsigned x1b = __shfl_sync(0xffffffffu, pj[mt][kf][1], src2);
                unsigned y0b = __shfl_sync(0xffffffffu, pj[mt][kf][2], src2);
                unsigned y1b = __shfl_sync(0xffffffffu, pj[mt][kf][3], src2);
                a[mt][0] = odd ? x1  : x0;    // P(gid,   tig)
                a[mt][1] = odd ? y1  : y0;    // P(gid+8, tig)
                a[mt][2] = odd ? x1b : x0b;   // P(gid,   tig+4)
                a[mt][3] = odd ? y1b : y0b;   // P(gid+8, tig+4)
            }
            #pragma unroll
            for (int nt = 0; nt < 8; ++nt) {
                const int cn = nt * 8;
                unsigned bf[2];
                bf[0] = VS(kk + tig    , cn + gid);
                bf[1] = VS(kk + tig + 4, cn + gid);
                mma8(acc_z[0][nt], a[0], bf);
                mma8(acc_z[1][nt], a[1], bf);
            }
        }
    }

    // ---- cross-warp (wks) Z reduction via smem, then store ----
    __syncthreads();
    float* stage = (float*)smem_dyn;      // 4 regions of 32x66 floats
    if (wks == 1) {
        float* st = stage + wqs * (32 * 66);
        #pragma unroll
        for (int mt = 0; mt < 2; ++mt) {
            const int r0 = mt * 16 + gid;
            #pragma unroll
            for (int nt = 0; nt < 8; ++nt) {
                const int c = nt * 8 + tig * 2;
                *(float2*)&st[r0 * 66 + c] = make_float2(acc_z[mt][nt][0], acc_z[mt][nt][1]);
                *(float2*)&st[(r0 + 8) * 66 + c] = make_float2(acc_z[mt][nt][2], acc_z[mt][nt][3]);
            }
        }
    }
    __syncthreads();
    if (wks == 0) {
        float* st = stage + wqs * (32 * 66);
        float* Zb = Z + (size_t)b * Ss * Dd + h * DEPTH;
        #pragma unroll
        for (int mt = 0; mt < 2; ++mt) {
            const int r0 = mt * 16 + gid;
            const int row = q0 + wqs * 32 + r0;
            #pragma unroll
            for (int nt = 0; nt < 8; ++nt) {
                const int c = nt * 8 + tig * 2;
                float2 p0 = *(float2*)&st[r0 * 66 + c];
                float2 p1 = *(float2*)&st[(r0 + 8) * 66 + c];
                *(float2*)&Zb[(size_t)row * Dd + c] =
                    make_float2(acc_z[mt][nt][0] + p0.x, acc_z[mt][nt][1] + p0.y);
                *(float2*)&Zb[(size_t)(row + 8) * Dd + c] =
                    make_float2(acc_z[mt][nt][2] + p1.x, acc_z[mt][nt][3] + p1.y);
            }
        }
    }
}

// ---------------------------------------------------------------
extern "C" void kernel_launch(void* const* d_in, const int* in_sizes, int n_in,
                              void* d_out, int out_size) {
    const float* x    = (const float*)d_in[0];
    const float* mask = (const float*)d_in[1];
    const float* Wq   = (const float*)d_in[2];
    const float* bq   = (const float*)d_in[3];
    const float* Wk   = (const float*)d_in[4];
    const float* bk   = (const float*)d_in[5];
    const float* Wv   = (const float*)d_in[6];
    const float* bv   = (const float*)d_in[7];
    const float* Wo   = (const float*)d_in[8];
    const float* bo   = (const float*)d_in[9];

    float *Qb, *Kb, *Vb, *Zb, *attn_scr, *out_scr, *rowpart, *invp;
    cudaGetSymbolAddress((void**)&Qb, g_Q);
    cudaGetSymbolAddress((void**)&Kb, g_K);
    cudaGetSymbolAddress((void**)&Vb, g_V);
    cudaGetSymbolAddress((void**)&Zb, g_Z);
    cudaGetSymbolAddress((void**)&attn_scr, g_attn);
    cudaGetSymbolAddress((void**)&out_scr, g_out);
    cudaGetSymbolAddress((void**)&rowpart, g_rowpart);
    cudaGetSymbolAddress((void**)&invp, g_inv);

    float* out_ptr;
    float* attn_ptr;
    const long long osz = (long long)out_size;
    if (osz >= OUT_ELEMS + ATTN_ELEMS) {
        out_ptr  = (float*)d_out;
        attn_ptr = (float*)d_out + OUT_ELEMS;
    } else if (osz >= ATTN_ELEMS) {
        attn_ptr = (float*)d_out;
        out_ptr  = out_scr;
    } else {
        out_ptr  = (float*)d_out;
        attn_ptr = attn_scr;
    }

    const int PASS2_SMEM = 106496;   // 26624 u32
    cudaFuncSetAttribute(attn_pass2,
                         cudaFuncAttributeMaxDynamicSharedMemorySize, PASS2_SMEM);

    // QKV projections, fused into one launch (grid.z = which projection)
    {
        dim3 grid(Dd / 128, MROWS / 128, 3);
        qkv_tc<<<grid, 256>>>(x, Wq, Wk, Wv, bq, bk, bv, Qb, Kb, Vb);
    }

    // pass 1: row sums of exp(logits)  (no big store)
    {
        dim3 grid(Ss / 128, Ss / 128, Bb * Hh);
        logits_sums_tc<<<grid, 512>>>(Qb, Kb, mask, rowpart);
    }

    // 1/rowsum
    rowsum_inv<<<(Bb * Hh * Ss) / 256, 256>>>(rowpart, invp);

    // pass 2: recompute S, write normalized attn, Z = attn @ V (register P)
    {
        dim3 grid(Ss / 128, Bb * Hh);
        attn_pass2<<<grid, 256, PASS2_SMEM>>>(Qb, Kb, Vb, mask, invp, attn_ptr, Zb);
    }

    // out = Z @ Wo + bo
    {
        dim3 grid(Dd / 128, MROWS / 128);
        gemm_tc<<<grid, 256>>>(Zb, Wo, bo, out_ptr, MROWS, Dd, Dd);
    }
}